// round 9
// baseline (speedup 1.0000x reference)
#include <cuda_runtime.h>
#include <cuda_bf16.h>

// 16k -> 24k Kaldi polyphase resampler — direct-streaming design (no data SMEM).
//   in_unit = 2, out_unit = 3, W = 13 taps, first_indices = {-6,-5,-4}
//   out[c, 3u+p] = sum_{j=0}^{12} x[c, 2u + (p-6) + j] * w[p][j]   (zero-padded)
//
// Thread q handles units (2q, 2q+1) = outputs [6q, 6q+6): loads its input
// window x[4q-8 .. 4q+11] with 5 coalesced LDG.128 (base 4q-8 is 16B-aligned,
// lane stride 16B), computes 74 FMAs, stores 3x float2 (6q is even -> 8B ok).
// Neighbor-thread window overlap is served by L1 hits; DRAM read traffic
// stays at the 128MB floor. No __syncthreads on the hot path -> warps keep
// independent LDGs in flight continuously (latency-bound fix from R8).
//
// Weight structure (exact identities of the reference filter construction;
// values still READ from the weights input):
//   w0[j] symmetric about tap 6  -> 7 unique values w0u[k] = w0[6+k]
//   w2[j] = w1[11-j] (dt negation), w1[12] = w2[12] = 0 (|dt| >= window)
// => only 19 weight registers instead of 39.

#define RS_NT 256

__global__ __launch_bounds__(RS_NT, 4)
void resample_16k_24k_kernel(const float* __restrict__ x,
                             const float* __restrict__ w,
                             float* __restrict__ y,
                             int L, int tot, int pairs)
{
    __shared__ float swt[20];   // [0..6] = w0u, [8..19] = w1

    // Stage the 19 structurally-unique weights (broadcast LDS later).
    if (threadIdx.x < 7)  swt[threadIdx.x] = w[6 + threadIdx.x];          // w0 upper half
    if (threadIdx.x < 12) swt[8 + threadIdx.x] = w[13 + threadIdx.x];     // w1[0..11]
    __syncthreads();

    const int q = blockIdx.x * RS_NT + threadIdx.x;   // unit-pair index
    if (q >= pairs) return;

    const int c  = blockIdx.y;
    const float* xc = x + (size_t)c * (size_t)L;
    float*       yc = y + (size_t)c * (size_t)tot;

    // Weights to registers (19 broadcast LDS).
    float w0u[7], w1[12];
    #pragma unroll
    for (int k = 0; k < 7; k++)  w0u[k] = swt[k];
    #pragma unroll
    for (int j = 0; j < 12; j++) w1[j] = swt[8 + j];

    // Load window d[i] = x[g0 + i], i in [0, 20), g0 = 4q - 8 (16B-aligned).
    const int g0 = 4 * q - 8;
    float d[20];
    if (g0 >= 0 && g0 + 20 <= L) {
        const float4* xg = (const float4*)(xc + g0);
        const float4 v0 = __ldg(xg + 0);
        const float4 v1 = __ldg(xg + 1);
        const float4 v2 = __ldg(xg + 2);
        const float4 v3 = __ldg(xg + 3);
        const float4 v4 = __ldg(xg + 4);
        d[0]=v0.x; d[1]=v0.y; d[2]=v0.z; d[3]=v0.w;
        d[4]=v1.x; d[5]=v1.y; d[6]=v1.z; d[7]=v1.w;
        d[8]=v2.x; d[9]=v2.y; d[10]=v2.z; d[11]=v2.w;
        d[12]=v3.x; d[13]=v3.y; d[14]=v3.z; d[15]=v3.w;
        d[16]=v4.x; d[17]=v4.y; d[18]=v4.z; d[19]=v4.w;
    } else {
        #pragma unroll
        for (int i = 0; i < 20; i++) {
            const int g = g0 + i;
            d[i] = (g >= 0 && g < L) ? __ldg(xc + g) : 0.0f;
        }
    }

    // a[3*uu + p]: unit 2q+uu, phase p. Sample x[4q + 2uu + p - 6 + j] = d[2uu + p + 2 + j].
    float a[6];
    #pragma unroll
    for (int uu = 0; uu < 2; uu++) {
        const int o = 2 * uu;
        // phase 0: 13 taps, symmetric weights
        {
            float acc = 0.0f;
            #pragma unroll
            for (int j = 0; j < 13; j++) {
                const float wj = (j <= 6) ? w0u[6 - j] : w0u[j - 6];
                acc = fmaf(d[o + 2 + j], wj, acc);
            }
            a[3 * uu + 0] = acc;
        }
        // phase 1: 12 taps (tap 12 is exactly zero)
        {
            float acc = 0.0f;
            #pragma unroll
            for (int j = 0; j < 12; j++)
                acc = fmaf(d[o + 3 + j], w1[j], acc);
            a[3 * uu + 1] = acc;
        }
        // phase 2: 12 taps, w2[j] = w1[11-j] (tap 12 is exactly zero)
        {
            float acc = 0.0f;
            #pragma unroll
            for (int j = 0; j < 12; j++)
                acc = fmaf(d[o + 4 + j], w1[11 - j], acc);
            a[3 * uu + 2] = acc;
        }
    }

    // Store outputs [6q, 6q+6): 6q is even -> float2 stores are 8B-aligned.
    const int n0 = 6 * q;
    if (n0 + 6 <= tot) {
        float2* yp = (float2*)(yc + n0);
        yp[0] = make_float2(a[0], a[1]);
        yp[1] = make_float2(a[2], a[3]);
        yp[2] = make_float2(a[4], a[5]);
    } else {
        #pragma unroll
        for (int k = 0; k < 6; k++)
            if (n0 + k < tot) yc[n0 + k] = a[k];
    }
}

extern "C" void kernel_launch(void* const* d_in, const int* in_sizes, int n_in,
                              void* d_out, int out_size)
{
    // Inputs: waveform [8, L] float32, weights [3, 13] float32 (defensive
    // about ordering via element counts).
    int wav_i = 0, wts_i = 1;
    if (n_in >= 2 && in_sizes[0] < in_sizes[1]) { wav_i = 1; wts_i = 0; }

    const float* wav = (const float*)d_in[wav_i];
    const float* wts = (const float*)d_in[wts_i];
    float* out = (float*)d_out;

    const int C     = 8;
    const int L     = in_sizes[wav_i] / C;
    const int tot   = out_size / C;            // = 3L/2 = 6,000,000
    const int pairs = (tot + 5) / 6;           // unit-pairs per channel

    dim3 grid((pairs + RS_NT - 1) / RS_NT, C);
    resample_16k_24k_kernel<<<grid, RS_NT>>>(wav, wts, out, L, tot, pairs);
}

// round 11
// speedup vs baseline: 1.2990x; 1.2990x over previous
#include <cuda_runtime.h>
#include <cuda_bf16.h>

// 16k -> 24k Kaldi polyphase resampler.
//   in_unit = 2, out_unit = 3, W = 13 taps, first_indices = {-6,-5,-4}
//   out[c, 3u+p] = sum_{j=0}^{12} x[c, 2u + (p-6) + j] * w[p][j]   (zero-padded)
//
// R9 design: R5's SMEM-tile skeleton (fastest so far; occupancy-dominated
// workload) with occupancy pushed to 6 CTAs/SM (75%) via a 42-reg cap, plus
// occupancy-neutral savings:
//   - LDG.128 staging (base 2*u0-8 is 16B-aligned)
//   - explicit d-window register blocking: 5 conflict-free LDS.128 per group
//   - weight symmetry (exact in the reference filter construction):
//       w0 symmetric about tap 6 (7 unique), w2[j] = w1[11-j],
//       w1[12] = w2[12] = 0  -> 19 unique weights, 74 FMAs per unit-pair
//     weights stay in SMEM (broadcast LDS) to protect the register cap.

#define RS_NT    256                      // threads per CTA
#define RS_G     4                        // groups (unit-pairs per thread)
#define RS_PAIRS (RS_NT * RS_G)           // 1024 pairs per CTA
#define RS_UPB   (RS_PAIRS * 2)           // 2048 units per CTA
#define RS_SEGF  (4 * RS_PAIRS + 16)      // 4112 staged floats (16.1 KB)
#define RS_NF4   (RS_SEGF / 4)            // 1028 float4s

__global__ __launch_bounds__(RS_NT, 6)
void resample_16k_24k_kernel(const float* __restrict__ x,
                             const float* __restrict__ w,
                             float* __restrict__ y,
                             int L, int tot)
{
    __shared__ __align__(16) float s[RS_SEGF];
    __shared__ float swt[20];   // [0..6] = w0u (upper half of w0), [8..19] = w1[0..11]

    const int c  = blockIdx.y;
    const int u0 = blockIdx.x * RS_UPB;
    const float* xc = x + (size_t)c * (size_t)L;
    float*       yc = y + (size_t)c * (size_t)tot;

    // Stage the 19 structurally-unique weights.
    if (threadIdx.x < 7)  swt[threadIdx.x]     = w[6 + threadIdx.x];   // w0[6..12]
    if (threadIdx.x < 12) swt[8 + threadIdx.x] = w[13 + threadIdx.x];  // w1[0..11]

    // Stage input segment: s[i] = x[g0 + i], zero outside [0, L).
    const int g0 = 2 * u0 - 8;                       // multiple of 4
    if (g0 >= 0 && g0 + RS_SEGF <= L) {
        // Fast path: fully interior -> unpredicated LDG.128 / STS.128.
        const float4* xg = (const float4*)(xc + g0); // 16B-aligned
        float4* sg = (float4*)s;
        #pragma unroll
        for (int k = 0; k < RS_NF4 / RS_NT; k++) {   // 4 full rounds
            const int f = k * RS_NT + threadIdx.x;
            sg[f] = __ldg(xg + f);
        }
        if (threadIdx.x < RS_NF4 - (RS_NF4 / RS_NT) * RS_NT) {  // remainder: 4
            const int f = (RS_NF4 / RS_NT) * RS_NT + threadIdx.x;
            sg[f] = __ldg(xg + f);
        }
    } else {
        // Edge CTAs (first/last per channel): scalar bounds-checked staging.
        for (int i = threadIdx.x; i < RS_SEGF; i += RS_NT) {
            const int g = g0 + i;
            s[i] = (g >= 0 && g < L) ? __ldg(xc + g) : 0.0f;
        }
    }
    __syncthreads();

    const float4* s4 = (const float4*)s;

    #pragma unroll
    for (int gix = 0; gix < RS_G; gix++) {
        const int q = gix * RS_NT + threadIdx.x;     // local unit-pair index
        // d[t] = s[4q + t], t in [0, 20): 5 conflict-free LDS.128
        // (lane stride 16B). Used range is t in [2, 18].
        const float4 v0 = s4[q];
        const float4 v1 = s4[q + 1];
        const float4 v2 = s4[q + 2];
        const float4 v3 = s4[q + 3];
        const float4 v4 = s4[q + 4];
        const float d[20] = {v0.x, v0.y, v0.z, v0.w,
                             v1.x, v1.y, v1.z, v1.w,
                             v2.x, v2.y, v2.z, v2.w,
                             v3.x, v3.y, v3.z, v3.w,
                             v4.x, v4.y, v4.z, v4.w};

        // Units (u0+2q, u0+2q+1); sample for unit uu, phase p, tap j is
        // d[2*uu + p + 2 + j].
        float a[6];
        #pragma unroll
        for (int uu = 0; uu < 2; uu++) {
            const int o = 2 * uu;
            // phase 0: 13 taps, symmetric weights w0[j] = w0u[|j-6|]
            {
                float acc = 0.0f;
                #pragma unroll
                for (int j = 0; j < 13; j++) {
                    const float wj = (j <= 6) ? swt[6 - j] : swt[j - 6];
                    acc = fmaf(d[o + 2 + j], wj, acc);
                }
                a[3 * uu + 0] = acc;
            }
            // phase 1: 12 taps (tap 12 is exactly zero)
            {
                float acc = 0.0f;
                #pragma unroll
                for (int j = 0; j < 12; j++)
                    acc = fmaf(d[o + 3 + j], swt[8 + j], acc);
                a[3 * uu + 1] = acc;
            }
            // phase 2: 12 taps, w2[j] = w1[11-j] (tap 12 is exactly zero)
            {
                float acc = 0.0f;
                #pragma unroll
                for (int j = 0; j < 12; j++)
                    acc = fmaf(d[o + 4 + j], swt[8 + 11 - j], acc);
                a[3 * uu + 2] = acc;
            }
        }

        // Outputs [n0, n0+6): n0 is even -> 8B-aligned float2 stores.
        const int n0 = 3 * u0 + 6 * q;
        if (n0 + 6 <= tot) {
            float2* yp = (float2*)(yc + n0);
            yp[0] = make_float2(a[0], a[1]);
            yp[1] = make_float2(a[2], a[3]);
            yp[2] = make_float2(a[4], a[5]);
        } else {
            #pragma unroll
            for (int k = 0; k < 6; k++)
                if (n0 + k < tot) yc[n0 + k] = a[k];
        }
    }
}

extern "C" void kernel_launch(void* const* d_in, const int* in_sizes, int n_in,
                              void* d_out, int out_size)
{
    // Inputs: waveform [8, L] float32, weights [3, 13] float32 (defensive
    // about ordering via element counts).
    int wav_i = 0, wts_i = 1;
    if (n_in >= 2 && in_sizes[0] < in_sizes[1]) { wav_i = 1; wts_i = 0; }

    const float* wav = (const float*)d_in[wav_i];
    const float* wts = (const float*)d_in[wts_i];
    float* out = (float*)d_out;

    const int C   = 8;
    const int L   = in_sizes[wav_i] / C;
    const int tot = out_size / C;                 // = 3L/2 = 6,000,000
    const int tot_units = (tot + 2) / 3;          // ceil(tot / 3)

    dim3 grid((tot_units + RS_UPB - 1) / RS_UPB, C);
    resample_16k_24k_kernel<<<grid, RS_NT>>>(wav, wts, out, L, tot);
}

// round 12
// speedup vs baseline: 1.3141x; 1.0116x over previous
#include <cuda_runtime.h>
#include <cuda_bf16.h>
#include <cuda_pipeline.h>

// 16k -> 24k Kaldi polyphase resampler.
//   in_unit = 2, out_unit = 3, W = 13 taps, first_indices = {-6,-5,-4}
//   out[c, 3u+p] = sum_{j=0}^{12} x[c, 2u + (p-6) + j] * w[p][j]   (zero-padded)
//
// R11 design: cp.async double-buffered subtile pipeline. Each CTA processes
// RS_T=8 subtiles of 512 units; subtile t+1 is staged with cp.async (LDGSTS,
// no register landing) while subtile t is computed -> DRAM reads overlap
// compute instead of pulsing (front-batched LDG + barrier convoy was the ~55%
// DRAM cap across R5/R9/R11 variants). Compute per thread per subtile:
// one unit-pair window via 5 conflict-free LDS.128, 74 FMAs using exact
// weight symmetry (w0 symmetric, w2[j]=w1[11-j], tap12 of w1/w2 = 0,
// weights read from input and staged in SMEM), 3x 8B-aligned float2 stores.

#define RS_NT    256                      // threads per CTA
#define RS_T     8                        // subtiles per CTA
#define RS_SUBP  RS_NT                    // unit-pairs per subtile (256)
#define RS_SUBU  (2 * RS_SUBP)            // 512 units per subtile
#define RS_SEGF  (4 * RS_SUBP + 16)       // 1040 staged floats per subtile
#define RS_NF4   (RS_SEGF / 4)            // 260 float4s
#define RS_UPB   (RS_T * RS_SUBU)         // 4096 units per CTA

__global__ __launch_bounds__(RS_NT, 6)
void resample_16k_24k_kernel(const float* __restrict__ x,
                             const float* __restrict__ w,
                             float* __restrict__ y,
                             int L, int tot)
{
    __shared__ __align__(16) float sbuf[2][RS_SEGF];
    __shared__ float swt[20];   // [0..6] = w0[6..12] (symmetric half), [8..19] = w1[0..11]

    const int c  = blockIdx.y;
    const int u0 = blockIdx.x * RS_UPB;
    const float* xc = x + (size_t)c * (size_t)L;
    float*       yc = y + (size_t)c * (size_t)tot;

    // Stage the 19 structurally-unique weights (visible after first barrier).
    if (threadIdx.x < 7)  swt[threadIdx.x]     = w[6 + threadIdx.x];   // w0[6..12]
    if (threadIdx.x < 12) swt[8 + threadIdx.x] = w[13 + threadIdx.x];  // w1[0..11]

    // Stage subtile t's segment (s[i] = x[gs + i], zero outside [0,L)) into buf.
    auto stage = [&](int t, int buf) {
        const int gs = 2 * u0 + 2 * RS_SUBU * t - 8;        // multiple of 4
        float* sb = sbuf[buf];
        if (gs >= 0 && gs + RS_SEGF <= L) {
            // Interior: cp.async 16B copies, no register landing, no stall.
            const float4* xg = (const float4*)(xc + gs);    // 16B-aligned
            float4* sg = (float4*)sb;
            __pipeline_memcpy_async(sg + threadIdx.x, xg + threadIdx.x, 16);
            if (threadIdx.x < RS_NF4 - RS_NT)               // 4 remainder float4s
                __pipeline_memcpy_async(sg + RS_NT + threadIdx.x,
                                        xg + RS_NT + threadIdx.x, 16);
        } else {
            // Edge subtiles: scalar bounds-checked staging (ordinary STS;
            // made visible by the barrier after the pipeline wait).
            for (int i = threadIdx.x; i < RS_SEGF; i += RS_NT) {
                const int g = gs + i;
                sb[i] = (g >= 0 && g < L) ? __ldg(xc + g) : 0.0f;
            }
        }
    };

    stage(0, 0);
    __pipeline_commit();

    for (int t = 0; t < RS_T; t++) {
        // Barrier: compute of subtile t-1 (reader of buf[(t+1)&1]) must finish
        // before stage(t+1) overwrites that buffer. Also publishes swt at t=0.
        __syncthreads();
        if (t + 1 < RS_T) stage(t + 1, (t + 1) & 1);
        __pipeline_commit();            // one group per iteration (may be empty)
        __pipeline_wait_prior(1);       // subtile t's group complete
        __syncthreads();                // all threads' copies + edge STS visible

        const float4* s4 = (const float4*)sbuf[t & 1];
        const int q = threadIdx.x;      // unit-pair within subtile
        // d[i] = s[4q + i], i in [0,20): 5 conflict-free LDS.128 (16B lane stride)
        const float4 v0 = s4[q];
        const float4 v1 = s4[q + 1];
        const float4 v2 = s4[q + 2];
        const float4 v3 = s4[q + 3];
        const float4 v4 = s4[q + 4];
        const float d[20] = {v0.x, v0.y, v0.z, v0.w,
                             v1.x, v1.y, v1.z, v1.w,
                             v2.x, v2.y, v2.z, v2.w,
                             v3.x, v3.y, v3.z, v3.w,
                             v4.x, v4.y, v4.z, v4.w};

        // Unit pair (2Q, 2Q+1), Q = u0/2-relative; sample for local unit uu,
        // phase p, tap j is d[2*uu + p + 2 + j].
        float a[6];
        #pragma unroll
        for (int uu = 0; uu < 2; uu++) {
            const int o = 2 * uu;
            {   // phase 0: 13 taps, symmetric weights w0[j] = swt[|j-6|]
                float acc = 0.0f;
                #pragma unroll
                for (int j = 0; j < 13; j++) {
                    const float wj = (j <= 6) ? swt[6 - j] : swt[j - 6];
                    acc = fmaf(d[o + 2 + j], wj, acc);
                }
                a[3 * uu + 0] = acc;
            }
            {   // phase 1: 12 taps (tap 12 exactly zero)
                float acc = 0.0f;
                #pragma unroll
                for (int j = 0; j < 12; j++)
                    acc = fmaf(d[o + 3 + j], swt[8 + j], acc);
                a[3 * uu + 1] = acc;
            }
            {   // phase 2: 12 taps, w2[j] = w1[11-j] (tap 12 exactly zero)
                float acc = 0.0f;
                #pragma unroll
                for (int j = 0; j < 12; j++)
                    acc = fmaf(d[o + 4 + j], swt[8 + 11 - j], acc);
                a[3 * uu + 2] = acc;
            }
        }

        // Outputs [n0, n0+6): n0 even -> 8B-aligned float2 stores.
        const int n0 = 3 * u0 + 3 * RS_SUBU * t + 6 * q;
        if (n0 + 6 <= tot) {
            float2* yp = (float2*)(yc + n0);
            yp[0] = make_float2(a[0], a[1]);
            yp[1] = make_float2(a[2], a[3]);
            yp[2] = make_float2(a[4], a[5]);
        } else {
            #pragma unroll
            for (int k = 0; k < 6; k++)
                if (n0 + k < tot) yc[n0 + k] = a[k];
        }
    }
}

extern "C" void kernel_launch(void* const* d_in, const int* in_sizes, int n_in,
                              void* d_out, int out_size)
{
    // Inputs: waveform [8, L] float32, weights [3, 13] float32 (defensive
    // about ordering via element counts).
    int wav_i = 0, wts_i = 1;
    if (n_in >= 2 && in_sizes[0] < in_sizes[1]) { wav_i = 1; wts_i = 0; }

    const float* wav = (const float*)d_in[wav_i];
    const float* wts = (const float*)d_in[wts_i];
    float* out = (float*)d_out;

    const int C   = 8;
    const int L   = in_sizes[wav_i] / C;
    const int tot = out_size / C;                 // = 3L/2 = 6,000,000
    const int tot_units = (tot + 2) / 3;          // ceil(tot / 3)

    dim3 grid((tot_units + RS_UPB - 1) / RS_UPB, C);
    resample_16k_24k_kernel<<<grid, RS_NT>>>(wav, wts, out, L, tot);
}